// round 1
// baseline (speedup 1.0000x reference)
#include <cuda_runtime.h>
#include <math.h>

#define BATCH 4
#define LEN 2048
#define DMODEL 1024
#define NH 8
#define DHEAD 128
#define MROWS (BATCH * LEN)

// Scratch (static __device__ arrays: the sanctioned no-alloc workaround)
__device__ float g_Q[NH * BATCH * LEN * DHEAD];    // [h][b][l][d]
__device__ float g_K[NH * BATCH * LEN * DHEAD];
__device__ float g_V[NH * BATCH * LEN * DHEAD];
__device__ float g_ctx[BATCH * LEN * DMODEL];      // [b][l][h*128+d]

// ---------------------------------------------------------------------------
// NT GEMM: C = A (M x K) @ W^T, W is (N x K) row-major. M=8192, N=K=1024.
// BM=BN=64, BK=16, 256 threads, 4x4 per thread, smem-transposed tiles.
// SCATTER=1: write into [H,B,L,DH] layout. SCATTER=0: plain row-major.
// ---------------------------------------------------------------------------
template <int SCATTER>
__global__ void __launch_bounds__(256)
gemm_nt_k(const float* __restrict__ A, const float* __restrict__ W,
          float* __restrict__ C)
{
    __shared__ float As[16 * 68];   // [k][m], pitch 68 keeps float4 alignment
    __shared__ float Ws[16 * 68];   // [k][n]

    const int tid = threadIdx.x;
    const int tx = tid & 15;
    const int ty = tid >> 4;
    const int m0 = blockIdx.x * 64;
    const int n0 = blockIdx.y * 64;

    const int lr = tid >> 2;          // 0..63 : tile row this thread loads
    const int lc = (tid & 3) * 4;     // 0,4,8,12 : k-offset (float4)

    const float* Ag = A + (size_t)(m0 + lr) * DMODEL + lc;
    const float* Wg = W + (size_t)(n0 + lr) * DMODEL + lc;

    float acc[4][4];
#pragma unroll
    for (int i = 0; i < 4; i++)
#pragma unroll
        for (int j = 0; j < 4; j++) acc[i][j] = 0.0f;

    for (int k0 = 0; k0 < DMODEL; k0 += 16) {
        const float4 av = *(const float4*)(Ag + k0);
        const float4 wv = *(const float4*)(Wg + k0);
        __syncthreads();   // previous iteration's readers are done
        As[(lc + 0) * 68 + lr] = av.x;
        As[(lc + 1) * 68 + lr] = av.y;
        As[(lc + 2) * 68 + lr] = av.z;
        As[(lc + 3) * 68 + lr] = av.w;
        Ws[(lc + 0) * 68 + lr] = wv.x;
        Ws[(lc + 1) * 68 + lr] = wv.y;
        Ws[(lc + 2) * 68 + lr] = wv.z;
        Ws[(lc + 3) * 68 + lr] = wv.w;
        __syncthreads();

#pragma unroll
        for (int kk = 0; kk < 16; kk++) {
            const float4 a = *(const float4*)(As + kk * 68 + 4 * ty);
            const float4 b = *(const float4*)(Ws + kk * 68 + 4 * tx);
            const float a4[4] = {a.x, a.y, a.z, a.w};
            const float b4[4] = {b.x, b.y, b.z, b.w};
#pragma unroll
            for (int i = 0; i < 4; i++)
#pragma unroll
                for (int j = 0; j < 4; j++) acc[i][j] += a4[i] * b4[j];
        }
    }

    if (SCATTER) {
        // n -> (h, d); block lies fully inside one head (n0 multiple of 64)
        const int bb = m0 >> 11;            // batch
        const int lbase = m0 & (LEN - 1);
        const int hh = n0 >> 7;
        const int dbase = (n0 & 127) + 4 * tx;
#pragma unroll
        for (int i = 0; i < 4; i++) {
            const int l = lbase + 4 * ty + i;
            float* dst = C + (((size_t)(hh * BATCH + bb) * LEN + l) << 7) + dbase;
            *(float4*)dst = make_float4(acc[i][0], acc[i][1], acc[i][2], acc[i][3]);
        }
    } else {
#pragma unroll
        for (int i = 0; i < 4; i++) {
            float* dst = C + (size_t)(m0 + 4 * ty + i) * DMODEL + n0 + 4 * tx;
            *(float4*)dst = make_float4(acc[i][0], acc[i][1], acc[i][2], acc[i][3]);
        }
    }
}

// ---------------------------------------------------------------------------
// Flash attention, fp32. Grid: (L/64 q-tiles, B, H). 256 threads (16x16).
// Q tile 64x128 (pre-scaled), K tile 64x128, online softmax over key tiles.
// Skips key tiles beyond seqlen; zero-fills masked query rows.
// ---------------------------------------------------------------------------
#define QP 68  // transposed-tile pitch (floats); multiple of 4 for float4
#define SMEM_ATTN ((2 * 128 * QP + 64 * 128 + 64 * 64) * (int)sizeof(float))

__global__ void __launch_bounds__(256)
attn_kernel(const int* __restrict__ seq)
{
    extern __shared__ float sm[];
    float* Qt = sm;                 // [128 kk][64 r] pitch QP
    float* Kt = Qt + 128 * QP;      // [128 kk][64 key] pitch QP
    float* Vs = Kt + 128 * QP;      // [64 key][128 d]
    float* Ps = Vs + 64 * 128;      // [64 q][64 key]

    const int tid = threadIdx.x;
    const int tx = tid & 15;
    const int ty = tid >> 4;
    const int qt = blockIdx.x, b = blockIdx.y, h = blockIdx.z;
    const int qbase = qt * 64;
    const int slen = seq[b];

    float* ctx = g_ctx + (size_t)b * LEN * DMODEL + (size_t)h * DHEAD;

    if (qbase >= slen) {
        // entire q tile masked -> zeros
#pragma unroll
        for (int it = 0; it < 8; it++) {
            const int f = tid + it * 256;         // float4 index 0..2047
            const int rr = f >> 5;
            const int cc = (f & 31) * 4;
            *(float4*)(ctx + (size_t)(qbase + rr) * DMODEL + cc) =
                make_float4(0.f, 0.f, 0.f, 0.f);
        }
        return;
    }

    const float* Qg = g_Q + (((size_t)h * BATCH + b) * LEN + qbase) * DHEAD;
    const float* Kg = g_K + (((size_t)h * BATCH + b) * LEN) * DHEAD;
    const float* Vg = g_V + (((size_t)h * BATCH + b) * LEN) * DHEAD;

    // Load Q transposed with softmax scale baked in.
    {
        const int r = tid & 63;
        const int c0 = tid >> 6;
        const float scl = 0.08838834764831845f;   // 1/sqrt(128)
#pragma unroll
        for (int it = 0; it < 8; it++) {
            const int c4 = c0 + it * 4;
            const float4 v = *(const float4*)(Qg + (size_t)r * DHEAD + c4 * 4);
            const int d = c4 * 4;
            Qt[(d + 0) * QP + r] = v.x * scl;
            Qt[(d + 1) * QP + r] = v.y * scl;
            Qt[(d + 2) * QP + r] = v.z * scl;
            Qt[(d + 3) * QP + r] = v.w * scl;
        }
    }

    float m_i[4], l_i[4], o[4][8];
#pragma unroll
    for (int i = 0; i < 4; i++) {
        m_i[i] = -1e30f;
        l_i[i] = 0.0f;
#pragma unroll
        for (int c = 0; c < 8; c++) o[i][c] = 0.0f;
    }

    const int nkt = (slen + 63) >> 6;
    for (int kt = 0; kt < nkt; kt++) {
        const int kb = kt * 64;
        __syncthreads();   // previous tile's P.V reads complete

        // K tile -> transposed smem
        {
            const int r = tid & 63;
            const int c0 = tid >> 6;
#pragma unroll
            for (int it = 0; it < 8; it++) {
                const int c4 = c0 + it * 4;
                const float4 v =
                    *(const float4*)(Kg + (size_t)(kb + r) * DHEAD + c4 * 4);
                const int d = c4 * 4;
                Kt[(d + 0) * QP + r] = v.x;
                Kt[(d + 1) * QP + r] = v.y;
                Kt[(d + 2) * QP + r] = v.z;
                Kt[(d + 3) * QP + r] = v.w;
            }
        }
        // V tile -> natural layout
        {
#pragma unroll
            for (int it = 0; it < 8; it++) {
                const int f = tid + it * 256;
                const int rr = f >> 5;
                const int cc = (f & 31) * 4;
                *(float4*)(Vs + rr * 128 + cc) =
                    *(const float4*)(Vg + (size_t)(kb + rr) * DHEAD + cc);
            }
        }
        __syncthreads();

        // S = Q K^T (scaled)
        float s[4][4];
#pragma unroll
        for (int i = 0; i < 4; i++)
#pragma unroll
            for (int j = 0; j < 4; j++) s[i][j] = 0.0f;

#pragma unroll 8
        for (int kk = 0; kk < 128; kk++) {
            const float4 a = *(const float4*)(Qt + kk * QP + 4 * ty);
            const float4 bb = *(const float4*)(Kt + kk * QP + 4 * tx);
            const float a4[4] = {a.x, a.y, a.z, a.w};
            const float b4[4] = {bb.x, bb.y, bb.z, bb.w};
#pragma unroll
            for (int i = 0; i < 4; i++)
#pragma unroll
                for (int j = 0; j < 4; j++) s[i][j] += a4[i] * b4[j];
        }

        // key mask
#pragma unroll
        for (int j = 0; j < 4; j++) {
            if (kb + 4 * tx + j >= slen) {
                s[0][j] = -1e30f; s[1][j] = -1e30f;
                s[2][j] = -1e30f; s[3][j] = -1e30f;
            }
        }

        // online softmax per row
#pragma unroll
        for (int i = 0; i < 4; i++) {
            float mt = fmaxf(fmaxf(s[i][0], s[i][1]), fmaxf(s[i][2], s[i][3]));
#pragma unroll
            for (int off = 8; off > 0; off >>= 1)
                mt = fmaxf(mt, __shfl_xor_sync(0xffffffffu, mt, off));
            const float mn = fmaxf(m_i[i], mt);
            const float sc = __expf(m_i[i] - mn);
            const float p0 = __expf(s[i][0] - mn);
            const float p1 = __expf(s[i][1] - mn);
            const float p2 = __expf(s[i][2] - mn);
            const float p3 = __expf(s[i][3] - mn);
            float rs = (p0 + p1) + (p2 + p3);
#pragma unroll
            for (int off = 8; off > 0; off >>= 1)
                rs += __shfl_xor_sync(0xffffffffu, rs, off);
            l_i[i] = l_i[i] * sc + rs;
            m_i[i] = mn;
#pragma unroll
            for (int c = 0; c < 8; c++) o[i][c] *= sc;
            *(float4*)(Ps + (4 * ty + i) * 64 + 4 * tx) =
                make_float4(p0, p1, p2, p3);
        }
        __syncthreads();

        // O += P @ V
#pragma unroll 2
        for (int j = 0; j < 64; j++) {
            const float4 v0 = *(const float4*)(Vs + j * 128 + 8 * tx);
            const float4 v1 = *(const float4*)(Vs + j * 128 + 8 * tx + 4);
#pragma unroll
            for (int i = 0; i < 4; i++) {
                const float p = Ps[(4 * ty + i) * 64 + j];
                o[i][0] += p * v0.x; o[i][1] += p * v0.y;
                o[i][2] += p * v0.z; o[i][3] += p * v0.w;
                o[i][4] += p * v1.x; o[i][5] += p * v1.y;
                o[i][6] += p * v1.z; o[i][7] += p * v1.w;
            }
        }
    }

    // epilogue: divide by l, apply query mask, store context
#pragma unroll
    for (int i = 0; i < 4; i++) {
        const int q = qbase + 4 * ty + i;
        const float inv = (q < slen) ? (1.0f / l_i[i]) : 0.0f;
        float* dst = ctx + (size_t)q * DMODEL + 8 * tx;
        *(float4*)(dst + 0) = make_float4(o[i][0] * inv, o[i][1] * inv,
                                          o[i][2] * inv, o[i][3] * inv);
        *(float4*)(dst + 4) = make_float4(o[i][4] * inv, o[i][5] * inv,
                                          o[i][6] * inv, o[i][7] * inv);
    }
}

// ---------------------------------------------------------------------------
extern "C" void kernel_launch(void* const* d_in, const int* in_sizes, int n_in,
                              void* d_out, int out_size)
{
    (void)in_sizes; (void)n_in; (void)out_size;
    const float* queries = (const float*)d_in[0];
    const float* keys    = (const float*)d_in[1];
    const int*   seqlen  = (const int*)d_in[2];
    const float* Wq      = (const float*)d_in[3];
    const float* Wk      = (const float*)d_in[4];
    const float* Wv      = (const float*)d_in[5];
    const float* Wo      = (const float*)d_in[6];
    float* out = (float*)d_out;

    void *pQ, *pK, *pV, *pC;
    cudaGetSymbolAddress(&pQ, g_Q);
    cudaGetSymbolAddress(&pK, g_K);
    cudaGetSymbolAddress(&pV, g_V);
    cudaGetSymbolAddress(&pC, g_ctx);

    const dim3 gg(MROWS / 64, DMODEL / 64);
    gemm_nt_k<1><<<gg, 256>>>(queries, Wq, (float*)pQ);
    gemm_nt_k<1><<<gg, 256>>>(keys,    Wk, (float*)pK);
    gemm_nt_k<1><<<gg, 256>>>(keys,    Wv, (float*)pV);

    cudaFuncSetAttribute(attn_kernel,
                         cudaFuncAttributeMaxDynamicSharedMemorySize,
                         SMEM_ATTN);
    attn_kernel<<<dim3(LEN / 64, BATCH, NH), 256, SMEM_ATTN>>>(seqlen);

    gemm_nt_k<0><<<gg, 256>>>((const float*)pC, Wo, out);
}

// round 3
// speedup vs baseline: 1.9031x; 1.9031x over previous
#include <cuda_runtime.h>
#include <cstdint>
#include <math.h>

#define BATCH 4
#define LEN 2048
#define DMODEL 1024
#define NH 8
#define DHEAD 128
#define MROWS (BATCH * LEN)

// Scratch (static __device__ arrays: the sanctioned no-alloc workaround)
__device__ float g_Q[NH * BATCH * LEN * DHEAD];    // [h][b][l][d]
__device__ float g_K[NH * BATCH * LEN * DHEAD];
__device__ float g_V[NH * BATCH * LEN * DHEAD];
__device__ float g_ctx[BATCH * LEN * DMODEL];      // [b][l][h*128+d]

// ---------------------------------------------------------------------------
// tf32 helpers (compute_103-legal; no tcgen05)
// ---------------------------------------------------------------------------
__device__ __forceinline__ uint32_t f2tf32(float x) {
    uint32_t r;
    asm("cvt.rna.tf32.f32 %0, %1;" : "=r"(r) : "f"(x));
    return r;
}

__device__ __forceinline__ void mma_tf32(float& d0, float& d1, float& d2,
                                         float& d3, uint32_t a0, uint32_t a1,
                                         uint32_t a2, uint32_t a3, uint32_t b0,
                                         uint32_t b1) {
    asm volatile(
        "mma.sync.aligned.m16n8k8.row.col.f32.tf32.tf32.f32 "
        "{%0,%1,%2,%3}, {%4,%5,%6,%7}, {%8,%9}, {%0,%1,%2,%3};"
        : "+f"(d0), "+f"(d1), "+f"(d2), "+f"(d3)
        : "r"(a0), "r"(a1), "r"(a2), "r"(a3), "r"(b0), "r"(b1));
}

// ===========================================================================
// tf32 mma.sync NT-GEMM: C[M x N] = A[M x K] @ W^T, W row-major (N x K).
// CTA tile 128x128x16, 8 warps (2 m x 4 n), warp tile 64x32.
// Fragment layout (m16n8k8.row.col):
//   A: a0=[r][c] a1=[r+8][c] a2=[r][c+4] a3=[r+8][c+4]   r=lane>>2 c=lane&3
//   B (from W[n][k]): b0=W[n0+(lane>>2)][c] b1=W[n0+(lane>>2)][c+4]
//   C: c0=[r][2c] c1=[r][2c+1] c2=[r+8][2c] c3=[r+8][2c+1]
// SCATTER=1 writes into [H,B,L,DH]; SCATTER=0 plain row-major.
// ===========================================================================
#define SP 20   // smem pitch (floats): 4-aligned, conflict-free for frag LDS

template <int SCATTER>
__global__ void __launch_bounds__(256)
gemm_mma(const float* __restrict__ A, const float* __restrict__ W,
         float* __restrict__ C)
{
    __shared__ uint32_t As[128 * SP];
    __shared__ uint32_t Ws[128 * SP];

    const int tid = threadIdx.x;
    const int wid = tid >> 5;
    const int lane = tid & 31;
    const int wm = (wid >> 2) * 64;     // warp m offset in tile (0 / 64)
    const int wn = (wid & 3) * 32;      // warp n offset in tile
    const int r = lane >> 2;
    const int c = lane & 3;
    const int m0 = blockIdx.x * 128;
    const int n0 = blockIdx.y * 128;

    // global load mapping: 2 float4 per tile per thread
    const int grow0 = tid >> 2;                 // 0..63
    const int grow1 = grow0 + 64;               // 64..127
    const int gcol = (tid & 3) * 4;

    const float* Ag0 = A + (size_t)(m0 + grow0) * DMODEL + gcol;
    const float* Ag1 = A + (size_t)(m0 + grow1) * DMODEL + gcol;
    const float* Wg0 = W + (size_t)(n0 + grow0) * DMODEL + gcol;
    const float* Wg1 = W + (size_t)(n0 + grow1) * DMODEL + gcol;

    float acc[4][4][4];
#pragma unroll
    for (int i = 0; i < 4; i++)
#pragma unroll
        for (int j = 0; j < 4; j++)
#pragma unroll
            for (int q = 0; q < 4; q++) acc[i][j][q] = 0.0f;

    for (int k0 = 0; k0 < DMODEL; k0 += 16) {
        const float4 a0 = *(const float4*)(Ag0 + k0);
        const float4 a1 = *(const float4*)(Ag1 + k0);
        const float4 w0 = *(const float4*)(Wg0 + k0);
        const float4 w1 = *(const float4*)(Wg1 + k0);
        __syncthreads();   // previous iteration's fragment reads done
        {
            uint32_t* pa0 = As + grow0 * SP + gcol;
            uint32_t* pa1 = As + grow1 * SP + gcol;
            uint32_t* pw0 = Ws + grow0 * SP + gcol;
            uint32_t* pw1 = Ws + grow1 * SP + gcol;
            pa0[0] = f2tf32(a0.x); pa0[1] = f2tf32(a0.y);
            pa0[2] = f2tf32(a0.z); pa0[3] = f2tf32(a0.w);
            pa1[0] = f2tf32(a1.x); pa1[1] = f2tf32(a1.y);
            pa1[2] = f2tf32(a1.z); pa1[3] = f2tf32(a1.w);
            pw0[0] = f2tf32(w0.x); pw0[1] = f2tf32(w0.y);
            pw0[2] = f2tf32(w0.z); pw0[3] = f2tf32(w0.w);
            pw1[0] = f2tf32(w1.x); pw1[1] = f2tf32(w1.y);
            pw1[2] = f2tf32(w1.z); pw1[3] = f2tf32(w1.w);
        }
        __syncthreads();

#pragma unroll
        for (int ks = 0; ks < 2; ks++) {
            const int kc = ks * 8 + c;
            uint32_t af[4][4];
#pragma unroll
            for (int mt = 0; mt < 4; mt++) {
                const int m = wm + mt * 16;
                af[mt][0] = As[(m + r) * SP + kc];
                af[mt][1] = As[(m + r + 8) * SP + kc];
                af[mt][2] = As[(m + r) * SP + kc + 4];
                af[mt][3] = As[(m + r + 8) * SP + kc + 4];
            }
            uint32_t bf[4][2];
#pragma unroll
            for (int nt = 0; nt < 4; nt++) {
                const int n = wn + nt * 8 + r;
                bf[nt][0] = Ws[n * SP + kc];
                bf[nt][1] = Ws[n * SP + kc + 4];
            }
#pragma unroll
            for (int mt = 0; mt < 4; mt++)
#pragma unroll
                for (int nt = 0; nt < 4; nt++)
                    mma_tf32(acc[mt][nt][0], acc[mt][nt][1], acc[mt][nt][2],
                             acc[mt][nt][3], af[mt][0], af[mt][1], af[mt][2],
                             af[mt][3], bf[nt][0], bf[nt][1]);
        }
    }

    // epilogue
#pragma unroll
    for (int mt = 0; mt < 4; mt++) {
#pragma unroll
        for (int half = 0; half < 2; half++) {
            const int mrow = m0 + wm + mt * 16 + r + half * 8;
            float* dst;
            if (SCATTER) {
                const int bb = mrow >> 11;
                const int ll = mrow & (LEN - 1);
                const int hh = n0 >> 7;   // BN=128=DHEAD: one head per block col
                dst = C + (((size_t)(hh * BATCH + bb) * LEN + ll) << 7);
            } else {
                dst = C + (size_t)mrow * DMODEL + n0;
            }
#pragma unroll
            for (int nt = 0; nt < 4; nt++) {
                const int ncol = wn + nt * 8 + 2 * c;
                *(float2*)(dst + ncol) =
                    make_float2(acc[mt][nt][half * 2], acc[mt][nt][half * 2 + 1]);
            }
        }
    }
}

// ===========================================================================
// Flash attention, fp32 SIMT.
// ===========================================================================
#define QP 68
#define SMEM_ATTN ((2 * 128 * QP + 64 * 128 + 64 * 64) * (int)sizeof(float))

__global__ void __launch_bounds__(256)
attn_kernel(const int* __restrict__ seq)
{
    extern __shared__ float sm[];
    float* Qt = sm;
    float* Kt = Qt + 128 * QP;
    float* Vs = Kt + 128 * QP;
    float* Ps = Vs + 64 * 128;

    const int tid = threadIdx.x;
    const int tx = tid & 15;
    const int ty = tid >> 4;
    const int qt = blockIdx.x, b = blockIdx.y, h = blockIdx.z;
    const int qbase = qt * 64;
    const int slen = seq[b];

    float* ctx = g_ctx + (size_t)b * LEN * DMODEL + (size_t)h * DHEAD;

    if (qbase >= slen) {
#pragma unroll
        for (int it = 0; it < 8; it++) {
            const int f = tid + it * 256;
            const int rr = f >> 5;
            const int cc = (f & 31) * 4;
            *(float4*)(ctx + (size_t)(qbase + rr) * DMODEL + cc) =
                make_float4(0.f, 0.f, 0.f, 0.f);
        }
        return;
    }

    const float* Qg = g_Q + (((size_t)h * BATCH + b) * LEN + qbase) * DHEAD;
    const float* Kg = g_K + (((size_t)h * BATCH + b) * LEN) * DHEAD;
    const float* Vg = g_V + (((size_t)h * BATCH + b) * LEN) * DHEAD;

    {
        const int r = tid & 63;
        const int c0 = tid >> 6;
        const float scl = 0.08838834764831845f;
#pragma unroll
        for (int it = 0; it < 8; it++) {
            const int c4 = c0 + it * 4;
            const float4 v = *(const float4*)(Qg + (size_t)r * DHEAD + c4 * 4);
            const int d = c4 * 4;
            Qt[(d + 0) * QP + r] = v.x * scl;
            Qt[(d + 1) * QP + r] = v.y * scl;
            Qt[(d + 2) * QP + r] = v.z * scl;
            Qt[(d + 3) * QP + r] = v.w * scl;
        }
    }

    float m_i[4], l_i[4], o[4][8];
#pragma unroll
    for (int i = 0; i < 4; i++) {
        m_i[i] = -1e30f;
        l_i[i] = 0.0f;
#pragma unroll
        for (int c = 0; c < 8; c++) o[i][c] = 0.0f;
    }

    const int nkt = (slen + 63) >> 6;
    for (int kt = 0; kt < nkt; kt++) {
        const int kb = kt * 64;
        __syncthreads();

        {
            const int r = tid & 63;
            const int c0 = tid >> 6;
#pragma unroll
            for (int it = 0; it < 8; it++) {
                const int c4 = c0 + it * 4;
                const float4 v =
                    *(const float4*)(Kg + (size_t)(kb + r) * DHEAD + c4 * 4);
                const int d = c4 * 4;
                Kt[(d + 0) * QP + r] = v.x;
                Kt[(d + 1) * QP + r] = v.y;
                Kt[(d + 2) * QP + r] = v.z;
                Kt[(d + 3) * QP + r] = v.w;
            }
        }
        {
#pragma unroll
            for (int it = 0; it < 8; it++) {
                const int f = tid + it * 256;
                const int rr = f >> 5;
                const int cc = (f & 31) * 4;
                *(float4*)(Vs + rr * 128 + cc) =
                    *(const float4*)(Vg + (size_t)(kb + rr) * DHEAD + cc);
            }
        }
        __syncthreads();

        float s[4][4];
#pragma unroll
        for (int i = 0; i < 4; i++)
#pragma unroll
            for (int j = 0; j < 4; j++) s[i][j] = 0.0f;

#pragma unroll 8
        for (int kk = 0; kk < 128; kk++) {
            const float4 a = *(const float4*)(Qt + kk * QP + 4 * ty);
            const float4 bb = *(const float4*)(Kt + kk * QP + 4 * tx);
            const float a4[4] = {a.x, a.y, a.z, a.w};
            const float b4[4] = {bb.x, bb.y, bb.z, bb.w};
#pragma unroll
            for (int i = 0; i < 4; i++)
#pragma unroll
                for (int j = 0; j < 4; j++) s[i][j] += a4[i] * b4[j];
        }

#pragma unroll
        for (int j = 0; j < 4; j++) {
            if (kb + 4 * tx + j >= slen) {
                s[0][j] = -1e30f; s[1][j] = -1e30f;
                s[2][j] = -1e30f; s[3][j] = -1e30f;
            }
        }

#pragma unroll
        for (int i = 0; i < 4; i++) {
            float mt = fmaxf(fmaxf(s[i][0], s[i][1]), fmaxf(s[i][2], s[i][3]));
#pragma unroll
            for (int off = 8; off > 0; off >>= 1)
                mt = fmaxf(mt, __shfl_xor_sync(0xffffffffu, mt, off));
            const float mn = fmaxf(m_i[i], mt);
            const float sc = __expf(m_i[i] - mn);
            const float p0 = __expf(s[i][0] - mn);
            const float p1 = __expf(s[i][1] - mn);
            const float p2 = __expf(s[i][2] - mn);
            const float p3 = __expf(s[i][3] - mn);
            float rs = (p0 + p1) + (p2 + p3);
#pragma unroll
            for (int off = 8; off > 0; off >>= 1)
                rs += __shfl_xor_sync(0xffffffffu, rs, off);
            l_i[i] = l_i[i] * sc + rs;
            m_i[i] = mn;
#pragma unroll
            for (int c = 0; c < 8; c++) o[i][c] *= sc;
            *(float4*)(Ps + (4 * ty + i) * 64 + 4 * tx) =
                make_float4(p0, p1, p2, p3);
        }
        __syncthreads();

        // O += P @ V (P rows loaded as float4)
#pragma unroll 1
        for (int j4 = 0; j4 < 16; j4++) {
            float4 pr[4];
#pragma unroll
            for (int i = 0; i < 4; i++)
                pr[i] = *(const float4*)(Ps + (4 * ty + i) * 64 + 4 * j4);
#pragma unroll
            for (int jj = 0; jj < 4; jj++) {
                const int j = 4 * j4 + jj;
                const float4 v0 = *(const float4*)(Vs + j * 128 + 8 * tx);
                const float4 v1 = *(const float4*)(Vs + j * 128 + 8 * tx + 4);
                const float pv[4] = {
                    jj == 0 ? pr[0].x : jj == 1 ? pr[0].y : jj == 2 ? pr[0].z : pr[0].w,
                    jj == 0 ? pr[1].x : jj == 1 ? pr[1].y : jj == 2 ? pr[1].z : pr[1].w,
                    jj == 0 ? pr[2].x : jj == 1 ? pr[2].y : jj == 2 ? pr[2].z : pr[2].w,
                    jj == 0 ? pr[3].x : jj == 1 ? pr[3].y : jj == 2 ? pr[3].z : pr[3].w};
#pragma unroll
                for (int i = 0; i < 4; i++) {
                    const float p = pv[i];
                    o[i][0] += p * v0.x; o[i][1] += p * v0.y;
                    o[i][2] += p * v0.z; o[i][3] += p * v0.w;
                    o[i][4] += p * v1.x; o[i][5] += p * v1.y;
                    o[i][6] += p * v1.z; o[i][7] += p * v1.w;
                }
            }
        }
    }

#pragma unroll
    for (int i = 0; i < 4; i++) {
        const int q = qbase + 4 * ty + i;
        const float inv = (q < slen) ? (1.0f / l_i[i]) : 0.0f;
        float* dst = ctx + (size_t)q * DMODEL + 8 * tx;
        *(float4*)(dst + 0) = make_float4(o[i][0] * inv, o[i][1] * inv,
                                          o[i][2] * inv, o[i][3] * inv);
        *(float4*)(dst + 4) = make_float4(o[i][4] * inv, o[i][5] * inv,
                                          o[i][6] * inv, o[i][7] * inv);
    }
}

// ===========================================================================
extern "C" void kernel_launch(void* const* d_in, const int* in_sizes, int n_in,
                              void* d_out, int out_size)
{
    (void)in_sizes; (void)n_in; (void)out_size;
    const float* queries = (const float*)d_in[0];
    const float* keys    = (const float*)d_in[1];
    const int*   seqlen  = (const int*)d_in[2];
    const float* Wq      = (const float*)d_in[3];
    const float* Wk      = (const float*)d_in[4];
    const float* Wv      = (const float*)d_in[5];
    const float* Wo      = (const float*)d_in[6];
    float* out = (float*)d_out;

    void *pQ, *pK, *pV, *pC;
    cudaGetSymbolAddress(&pQ, g_Q);
    cudaGetSymbolAddress(&pK, g_K);
    cudaGetSymbolAddress(&pV, g_V);
    cudaGetSymbolAddress(&pC, g_ctx);

    cudaFuncSetAttribute(attn_kernel,
                         cudaFuncAttributeMaxDynamicSharedMemorySize,
                         SMEM_ATTN);

    const dim3 gg(MROWS / 128, DMODEL / 128);
    gemm_mma<1><<<gg, 256>>>(queries, Wq, (float*)pQ);
    gemm_mma<1><<<gg, 256>>>(keys,    Wk, (float*)pK);
    gemm_mma<1><<<gg, 256>>>(keys,    Wv, (float*)pV);

    attn_kernel<<<dim3(LEN / 64, BATCH, NH), 256, SMEM_ATTN>>>(seqlen);

    gemm_mma<0><<<gg, 256>>>((const float*)pC, Wo, out);
}

// round 4
// speedup vs baseline: 2.9562x; 1.5534x over previous
#include <cuda_runtime.h>
#include <cstdint>
#include <math.h>

#define BATCH 4
#define LEN 2048
#define DMODEL 1024
#define NH 8
#define DHEAD 128
#define MROWS (BATCH * LEN)

__device__ float g_Q[NH * BATCH * LEN * DHEAD];    // [h][b][l][d]
__device__ float g_K[NH * BATCH * LEN * DHEAD];
__device__ float g_V[NH * BATCH * LEN * DHEAD];
__device__ float g_ctx[BATCH * LEN * DMODEL];      // [b][l][h*128+d]

// ---------------------------------------------------------------------------
// tf32 helpers (compute_103-legal)
// ---------------------------------------------------------------------------
__device__ __forceinline__ uint32_t f2tf32(float x) {
    uint32_t r;
    asm("cvt.rna.tf32.f32 %0, %1;" : "=r"(r) : "f"(x));
    return r;
}

__device__ __forceinline__ void mma_tf32(float& d0, float& d1, float& d2,
                                         float& d3, uint32_t a0, uint32_t a1,
                                         uint32_t a2, uint32_t a3, uint32_t b0,
                                         uint32_t b1) {
    asm volatile(
        "mma.sync.aligned.m16n8k8.row.col.f32.tf32.tf32.f32 "
        "{%0,%1,%2,%3}, {%4,%5,%6,%7}, {%8,%9}, {%0,%1,%2,%3};"
        : "+f"(d0), "+f"(d1), "+f"(d2), "+f"(d3)
        : "r"(a0), "r"(a1), "r"(a2), "r"(a3), "r"(b0), "r"(b1));
}

// ===========================================================================
// tf32 mma.sync NT-GEMM (unchanged from R3 — verified fragment layouts)
// ===========================================================================
#define SP 20

template <int SCATTER>
__global__ void __launch_bounds__(256)
gemm_mma(const float* __restrict__ A, const float* __restrict__ W,
         float* __restrict__ C)
{
    __shared__ uint32_t As[128 * SP];
    __shared__ uint32_t Ws[128 * SP];

    const int tid = threadIdx.x;
    const int wid = tid >> 5;
    const int lane = tid & 31;
    const int wm = (wid >> 2) * 64;
    const int wn = (wid & 3) * 32;
    const int r = lane >> 2;
    const int c = lane & 3;
    const int m0 = blockIdx.x * 128;
    const int n0 = blockIdx.y * 128;

    const int grow0 = tid >> 2;
    const int grow1 = grow0 + 64;
    const int gcol = (tid & 3) * 4;

    const float* Ag0 = A + (size_t)(m0 + grow0) * DMODEL + gcol;
    const float* Ag1 = A + (size_t)(m0 + grow1) * DMODEL + gcol;
    const float* Wg0 = W + (size_t)(n0 + grow0) * DMODEL + gcol;
    const float* Wg1 = W + (size_t)(n0 + grow1) * DMODEL + gcol;

    float acc[4][4][4];
#pragma unroll
    for (int i = 0; i < 4; i++)
#pragma unroll
        for (int j = 0; j < 4; j++)
#pragma unroll
            for (int q = 0; q < 4; q++) acc[i][j][q] = 0.0f;

    for (int k0 = 0; k0 < DMODEL; k0 += 16) {
        const float4 a0 = *(const float4*)(Ag0 + k0);
        const float4 a1 = *(const float4*)(Ag1 + k0);
        const float4 w0 = *(const float4*)(Wg0 + k0);
        const float4 w1 = *(const float4*)(Wg1 + k0);
        __syncthreads();
        {
            uint32_t* pa0 = As + grow0 * SP + gcol;
            uint32_t* pa1 = As + grow1 * SP + gcol;
            uint32_t* pw0 = Ws + grow0 * SP + gcol;
            uint32_t* pw1 = Ws + grow1 * SP + gcol;
            pa0[0] = f2tf32(a0.x); pa0[1] = f2tf32(a0.y);
            pa0[2] = f2tf32(a0.z); pa0[3] = f2tf32(a0.w);
            pa1[0] = f2tf32(a1.x); pa1[1] = f2tf32(a1.y);
            pa1[2] = f2tf32(a1.z); pa1[3] = f2tf32(a1.w);
            pw0[0] = f2tf32(w0.x); pw0[1] = f2tf32(w0.y);
            pw0[2] = f2tf32(w0.z); pw0[3] = f2tf32(w0.w);
            pw1[0] = f2tf32(w1.x); pw1[1] = f2tf32(w1.y);
            pw1[2] = f2tf32(w1.z); pw1[3] = f2tf32(w1.w);
        }
        __syncthreads();

#pragma unroll
        for (int ks = 0; ks < 2; ks++) {
            const int kc = ks * 8 + c;
            uint32_t af[4][4];
#pragma unroll
            for (int mt = 0; mt < 4; mt++) {
                const int m = wm + mt * 16;
                af[mt][0] = As[(m + r) * SP + kc];
                af[mt][1] = As[(m + r + 8) * SP + kc];
                af[mt][2] = As[(m + r) * SP + kc + 4];
                af[mt][3] = As[(m + r + 8) * SP + kc + 4];
            }
            uint32_t bf[4][2];
#pragma unroll
            for (int nt = 0; nt < 4; nt++) {
                const int n = wn + nt * 8 + r;
                bf[nt][0] = Ws[n * SP + kc];
                bf[nt][1] = Ws[n * SP + kc + 4];
            }
#pragma unroll
            for (int mt = 0; mt < 4; mt++)
#pragma unroll
                for (int nt = 0; nt < 4; nt++)
                    mma_tf32(acc[mt][nt][0], acc[mt][nt][1], acc[mt][nt][2],
                             acc[mt][nt][3], af[mt][0], af[mt][1], af[mt][2],
                             af[mt][3], bf[nt][0], bf[nt][1]);
        }
    }

#pragma unroll
    for (int mt = 0; mt < 4; mt++) {
#pragma unroll
        for (int half = 0; half < 2; half++) {
            const int mrow = m0 + wm + mt * 16 + r + half * 8;
            float* dst;
            if (SCATTER) {
                const int bb = mrow >> 11;
                const int ll = mrow & (LEN - 1);
                const int hh = n0 >> 7;
                dst = C + (((size_t)(hh * BATCH + bb) * LEN + ll) << 7);
            } else {
                dst = C + (size_t)mrow * DMODEL + n0;
            }
#pragma unroll
            for (int nt = 0; nt < 4; nt++) {
                const int ncol = wn + nt * 8 + 2 * c;
                *(float2*)(dst + ncol) =
                    make_float2(acc[mt][nt][half * 2], acc[mt][nt][half * 2 + 1]);
            }
        }
    }
}

// ===========================================================================
// Flash attention via mma.sync tf32.
// CTA: 128 q-rows, 8 warps, each warp owns 16 q-rows end-to-end.
// Key tiles of 64. Q fragments hoisted to registers (reused all tiles).
// ===========================================================================
#define ASP 132   // Qs/Ks pitch (uint32): frag LDS banks = 4r+c, conflict-free
#define BSP 68    // Vt/Ps pitch
#define SMA_Q 0
#define SMA_K (128 * ASP)
#define SMA_V (SMA_K + 64 * ASP)
#define SMA_P (SMA_V + 128 * BSP)
#define SMA_TOT (SMA_P + 128 * BSP)                  // uint32 count
#define SMEM_ATTN (SMA_TOT * (int)sizeof(uint32_t))  // 171008 B

__global__ void __launch_bounds__(256)
attn_mma(const int* __restrict__ seq)
{
    extern __shared__ uint32_t sm[];
    uint32_t* Qs = sm + SMA_Q;
    uint32_t* Ks = sm + SMA_K;
    uint32_t* Vt = sm + SMA_V;   // [d][j] transposed
    uint32_t* Ps = sm + SMA_P;   // [q][j]

    const int tid = threadIdx.x;
    const int wid = tid >> 5;
    const int lane = tid & 31;
    const int r = lane >> 2;
    const int c = lane & 3;
    const int qt = blockIdx.x, b = blockIdx.y, h = blockIdx.z;
    const int qbase = qt * 128;
    const int slen = seq[b];
    const int q0 = wid * 16;             // warp's q-row block within tile

    float* ctx = g_ctx + (size_t)b * LEN * DMODEL + (size_t)h * DHEAD;

    if (qbase >= slen) {
#pragma unroll
        for (int it = 0; it < 16; it++) {
            const int f = tid + it * 256;
            const int row = f >> 5;
            const int col = (f & 31) * 4;
            *(float4*)(ctx + (size_t)(qbase + row) * DMODEL + col) =
                make_float4(0.f, 0.f, 0.f, 0.f);
        }
        return;
    }

    const float* Qg = g_Q + (((size_t)h * BATCH + b) * LEN + qbase) * DHEAD;
    const float* Kg = g_K + ((size_t)h * BATCH + b) * LEN * DHEAD;
    const float* Vg = g_V + ((size_t)h * BATCH + b) * LEN * DHEAD;

    // Load Q tile (scale baked in), convert to tf32
    {
        const float scl = 0.08838834764831845f;   // 1/sqrt(128)
#pragma unroll
        for (int it = 0; it < 16; it++) {
            const int f = tid + it * 256;
            const int row = f >> 5;
            const int col = (f & 31) * 4;
            const float4 v = *(const float4*)(Qg + (size_t)row * DHEAD + col);
            uint32_t* p = Qs + row * ASP + col;
            p[0] = f2tf32(v.x * scl); p[1] = f2tf32(v.y * scl);
            p[2] = f2tf32(v.z * scl); p[3] = f2tf32(v.w * scl);
        }
    }
    __syncthreads();

    // Hoist Q fragments: 16 k-steps x 4 regs
    uint32_t qf[16][4];
#pragma unroll
    for (int ks = 0; ks < 16; ks++) {
        const int kc = ks * 8 + c;
        qf[ks][0] = Qs[(q0 + r) * ASP + kc];
        qf[ks][1] = Qs[(q0 + r + 8) * ASP + kc];
        qf[ks][2] = Qs[(q0 + r) * ASP + kc + 4];
        qf[ks][3] = Qs[(q0 + r + 8) * ASP + kc + 4];
    }

    float o[16][4];
#pragma unroll
    for (int nt = 0; nt < 16; nt++)
#pragma unroll
        for (int q = 0; q < 4; q++) o[nt][q] = 0.0f;
    float m0v = -1e30f, m1v = -1e30f, l0 = 0.0f, l1 = 0.0f;

    const int nkt = (slen + 63) >> 6;
    for (int kt = 0; kt < nkt; kt++) {
        const int kb = kt * 64;
        __syncthreads();   // prior tile's Ks/Vt reads done

        // K tile 64x128 -> Ks (tf32)
#pragma unroll
        for (int it = 0; it < 8; it++) {
            const int f = tid + it * 256;
            const int row = f >> 5;
            const int col = (f & 31) * 4;
            const float4 v =
                *(const float4*)(Kg + (size_t)(kb + row) * DHEAD + col);
            uint32_t* p = Ks + row * ASP + col;
            p[0] = f2tf32(v.x); p[1] = f2tf32(v.y);
            p[2] = f2tf32(v.z); p[3] = f2tf32(v.w);
        }
        // V tile 64x128 -> Vt transposed [d][j] (tf32)
#pragma unroll
        for (int it = 0; it < 8; it++) {
            const int f = tid + it * 256;
            const int j = f >> 5;
            const int d = (f & 31) * 4;
            const float4 v =
                *(const float4*)(Vg + (size_t)(kb + j) * DHEAD + d);
            Vt[(d + 0) * BSP + j] = f2tf32(v.x);
            Vt[(d + 1) * BSP + j] = f2tf32(v.y);
            Vt[(d + 2) * BSP + j] = f2tf32(v.z);
            Vt[(d + 3) * BSP + j] = f2tf32(v.w);
        }
        __syncthreads();

        // S = Q K^T : 8 n-tiles (64 keys), 16 k-steps (d=128)
        float s[8][4];
#pragma unroll
        for (int nt = 0; nt < 8; nt++)
#pragma unroll
            for (int q = 0; q < 4; q++) s[nt][q] = 0.0f;

#pragma unroll
        for (int ks = 0; ks < 16; ks++) {
            const int kc = ks * 8 + c;
            uint32_t bf[8][2];
#pragma unroll
            for (int nt = 0; nt < 8; nt++) {
                bf[nt][0] = Ks[(nt * 8 + r) * ASP + kc];
                bf[nt][1] = Ks[(nt * 8 + r) * ASP + kc + 4];
            }
#pragma unroll
            for (int nt = 0; nt < 8; nt++)
                mma_tf32(s[nt][0], s[nt][1], s[nt][2], s[nt][3],
                         qf[ks][0], qf[ks][1], qf[ks][2], qf[ks][3],
                         bf[nt][0], bf[nt][1]);
        }

        // key mask
#pragma unroll
        for (int nt = 0; nt < 8; nt++) {
            const int j0 = kb + nt * 8 + 2 * c;
            if (j0 >= slen)     { s[nt][0] = -1e30f; s[nt][2] = -1e30f; }
            if (j0 + 1 >= slen) { s[nt][1] = -1e30f; s[nt][3] = -1e30f; }
        }

        // online softmax (rows r and r+8; quad reduce via shfl 1,2)
        float mt0 = -1e30f, mt1 = -1e30f;
#pragma unroll
        for (int nt = 0; nt < 8; nt++) {
            mt0 = fmaxf(mt0, fmaxf(s[nt][0], s[nt][1]));
            mt1 = fmaxf(mt1, fmaxf(s[nt][2], s[nt][3]));
        }
        mt0 = fmaxf(mt0, __shfl_xor_sync(0xffffffffu, mt0, 1));
        mt0 = fmaxf(mt0, __shfl_xor_sync(0xffffffffu, mt0, 2));
        mt1 = fmaxf(mt1, __shfl_xor_sync(0xffffffffu, mt1, 1));
        mt1 = fmaxf(mt1, __shfl_xor_sync(0xffffffffu, mt1, 2));

        const float mn0 = fmaxf(m0v, mt0);
        const float mn1 = fmaxf(m1v, mt1);
        const float sc0 = __expf(m0v - mn0);
        const float sc1 = __expf(m1v - mn1);
        m0v = mn0; m1v = mn1;

        float rs0 = 0.0f, rs1 = 0.0f;
#pragma unroll
        for (int nt = 0; nt < 8; nt++) {
            const float p0 = __expf(s[nt][0] - mn0);
            const float p1 = __expf(s[nt][1] - mn0);
            const float p2 = __expf(s[nt][2] - mn1);
            const float p3 = __expf(s[nt][3] - mn1);
            rs0 += p0 + p1;
            rs1 += p2 + p3;
            uint32_t* pa = Ps + (q0 + r) * BSP + nt * 8 + 2 * c;
            pa[0] = f2tf32(p0); pa[1] = f2tf32(p1);
            uint32_t* pb = Ps + (q0 + r + 8) * BSP + nt * 8 + 2 * c;
            pb[0] = f2tf32(p2); pb[1] = f2tf32(p3);
        }
        rs0 += __shfl_xor_sync(0xffffffffu, rs0, 1);
        rs0 += __shfl_xor_sync(0xffffffffu, rs0, 2);
        rs1 += __shfl_xor_sync(0xffffffffu, rs1, 1);
        rs1 += __shfl_xor_sync(0xffffffffu, rs1, 2);
        l0 = l0 * sc0 + rs0;
        l1 = l1 * sc1 + rs1;

#pragma unroll
        for (int nt = 0; nt < 16; nt++) {
            o[nt][0] *= sc0; o[nt][1] *= sc0;
            o[nt][2] *= sc1; o[nt][3] *= sc1;
        }
        __syncwarp();   // P stores visible to fragment reloads (same warp)

        // O += P @ V : 16 n-tiles (d=128), 8 k-steps (j=64)
#pragma unroll
        for (int ks = 0; ks < 8; ks++) {
            const int kc = ks * 8 + c;
            uint32_t af[4];
            af[0] = Ps[(q0 + r) * BSP + kc];
            af[1] = Ps[(q0 + r + 8) * BSP + kc];
            af[2] = Ps[(q0 + r) * BSP + kc + 4];
            af[3] = Ps[(q0 + r + 8) * BSP + kc + 4];
#pragma unroll
            for (int nt = 0; nt < 16; nt++) {
                const uint32_t b0 = Vt[(nt * 8 + r) * BSP + kc];
                const uint32_t b1 = Vt[(nt * 8 + r) * BSP + kc + 4];
                mma_tf32(o[nt][0], o[nt][1], o[nt][2], o[nt][3],
                         af[0], af[1], af[2], af[3], b0, b1);
            }
        }
    }

    // epilogue: /l, query mask, store
    const int qr0 = qbase + q0 + r;
    const int qr1 = qr0 + 8;
    const float inv0 = (qr0 < slen) ? (1.0f / l0) : 0.0f;
    const float inv1 = (qr1 < slen) ? (1.0f / l1) : 0.0f;
#pragma unroll
    for (int nt = 0; nt < 16; nt++) {
        const int col = nt * 8 + 2 * c;
        *(float2*)(ctx + (size_t)qr0 * DMODEL + col) =
            make_float2(o[nt][0] * inv0, o[nt][1] * inv0);
        *(float2*)(ctx + (size_t)qr1 * DMODEL + col) =
            make_float2(o[nt][2] * inv1, o[nt][3] * inv1);
    }
}

// ===========================================================================
extern "C" void kernel_launch(void* const* d_in, const int* in_sizes, int n_in,
                              void* d_out, int out_size)
{
    (void)in_sizes; (void)n_in; (void)out_size;
    const float* queries = (const float*)d_in[0];
    const float* keys    = (const float*)d_in[1];
    const int*   seqlen  = (const int*)d_in[2];
    const float* Wq      = (const float*)d_in[3];
    const float* Wk      = (const float*)d_in[4];
    const float* Wv      = (const float*)d_in[5];
    const float* Wo      = (const float*)d_in[6];
    float* out = (float*)d_out;

    void *pQ, *pK, *pV, *pC;
    cudaGetSymbolAddress(&pQ, g_Q);
    cudaGetSymbolAddress(&pK, g_K);
    cudaGetSymbolAddress(&pV, g_V);
    cudaGetSymbolAddress(&pC, g_ctx);

    cudaFuncSetAttribute(attn_mma,
                         cudaFuncAttributeMaxDynamicSharedMemorySize,
                         SMEM_ATTN);

    const dim3 gg(MROWS / 128, DMODEL / 128);
    gemm_mma<1><<<gg, 256>>>(queries, Wq, (float*)pQ);
    gemm_mma<1><<<gg, 256>>>(keys,    Wk, (float*)pK);
    gemm_mma<1><<<gg, 256>>>(keys,    Wv, (float*)pV);

    attn_mma<<<dim3(LEN / 128, BATCH, NH), 256, SMEM_ATTN>>>(seqlen);

    gemm_mma<0><<<gg, 256>>>((const float*)pC, Wo, out);
}